// round 12
// baseline (speedup 1.0000x reference)
#include <cuda_runtime.h>
#include <cuda_fp16.h>
#include <math.h>
#include <stdint.h>

// ---------------- compile-time problem shape ----------------
#define TT 4096    // B*S tokens
#define DD 1024
#define HH 2048
#define OO 1024
#define EE 8
#define NSHTILES (TT/128)                 // 32 shared-expert tiles
#define MAXTILES (71 + NSHTILES + 1)      // expert tiles (<=71) + shared + pad
#define BUFROWS (MAXTILES*128)

// ---------------- scratch (device globals) ----------------
__device__ __half g_xh   [(size_t)TT*DD];        // LN1 output (fp16)
__device__ __half g_hid2h[(size_t)BUFROWS*HH];   // hidden, compact (fp16)
__device__ float  g_eout2[(size_t)BUFROWS*OO];   // output, compact (fp32)
__device__ __half g_w1h [(size_t)EE*HH*DD];
__device__ __half g_w2h [(size_t)EE*OO*HH];
__device__ __half g_sw1h[(size_t)HH*DD];
__device__ __half g_sw2h[(size_t)OO*HH];

__device__ int   g_tki [TT*2];
__device__ float g_tkw [TT*2];
__device__ int   g_rank[TT*2];
__device__ int   g_perm[BUFROWS];
__device__ int   g_cursor[EE];
__device__ int   g_base[EE];
__device__ int   g_sbase;
__device__ int   g_tile_expert[MAXTILES];
__device__ int   g_tile_rows[MAXTILES];

// ---------------- PTX helpers (baseline features; legal on compute_103) ----------------
__device__ __forceinline__ uint32_t smem_u32(const void* p) {
    uint32_t a;
    asm("{ .reg .u64 t; cvta.to.shared.u64 t, %1; cvt.u32.u64 %0, t; }" : "=r"(a) : "l"(p));
    return a;
}
__device__ __forceinline__ void cpa16(uint32_t dst, const void* src) {
    asm volatile("cp.async.cg.shared.global [%0], [%1], 16;" :: "r"(dst), "l"(src));
}
#define CP_COMMIT() asm volatile("cp.async.commit_group;" ::: "memory")
#define CP_WAIT0()  asm volatile("cp.async.wait_group 0;" ::: "memory")
#define CP_WAIT1()  asm volatile("cp.async.wait_group 1;" ::: "memory")
#define CP_WAIT2()  asm volatile("cp.async.wait_group 2;" ::: "memory")

#define MMA_F16(c, a, b) \
    asm volatile("mma.sync.aligned.m16n8k16.row.col.f32.f16.f16.f32 " \
        "{%0,%1,%2,%3}, {%4,%5,%6,%7}, {%8,%9}, {%0,%1,%2,%3};" \
        : "+f"((c)[0]), "+f"((c)[1]), "+f"((c)[2]), "+f"((c)[3]) \
        : "r"((a)[0]), "r"((a)[1]), "r"((a)[2]), "r"((a)[3]), \
          "r"((b)[0]), "r"((b)[1]))

#define LDSM_X4(r0, r1, r2, r3, addr) \
    asm volatile("ldmatrix.sync.aligned.m8n8.x4.shared.b16 {%0,%1,%2,%3}, [%4];" \
        : "=r"(r0), "=r"(r1), "=r"(r2), "=r"(r3) : "r"(addr))

__device__ __forceinline__ float gelu_exact(float x) {
    return 0.5f * x * (1.0f + erff(x * 0.70710678118654752440f));
}

__device__ __forceinline__ void block_reduce2(float& s, float& s2, float* sh) {
    #pragma unroll
    for (int o = 16; o; o >>= 1) {
        s  += __shfl_down_sync(0xffffffffu, s,  o);
        s2 += __shfl_down_sync(0xffffffffu, s2, o);
    }
    int w = threadIdx.x >> 5, l = threadIdx.x & 31;
    if (l == 0) { sh[w] = s; sh[8 + w] = s2; }
    __syncthreads();
    if (threadIdx.x == 0) {
        float a = 0.f, b = 0.f;
        #pragma unroll
        for (int i = 0; i < 8; i++) { a += sh[i]; b += sh[8 + i]; }
        sh[0] = a; sh[8] = b;
    }
    __syncthreads();
    s = sh[0]; s2 = sh[8];
}

// ================ fused prep: LN1+router (blocks 0..TT) | weight cvt (rest) ================
#define N8_EW1 (EE*HH*DD/8)
#define N8_EW2 (EE*OO*HH/8)
#define N8_SW1 (HH*DD/8)
#define N8_SW2 (OO*HH/8)
#define N8_ALL (N8_EW1 + N8_EW2 + N8_SW1 + N8_SW2)
#define CVT_BLOCKS ((N8_ALL + 4*256 - 1) / (4*256))
#define PREP_BLOCKS (TT + CVT_BLOCKS)

__global__ __launch_bounds__(256)
void prep_kernel(const float* __restrict__ x,
                 const float* __restrict__ g,
                 const float* __restrict__ b,
                 const float* __restrict__ rw,
                 const float* __restrict__ rb,
                 const float4* __restrict__ ew1, const float4* __restrict__ ew2,
                 const float4* __restrict__ sw1, const float4* __restrict__ sw2) {
    int tid = threadIdx.x;
    if (blockIdx.x >= TT) {
        int i0 = (blockIdx.x - TT) * 256 + tid;
        const int stride = CVT_BLOCKS * 256;
        #pragma unroll
        for (int k = 0; k < 4; k++) {
            int i = i0 + k * stride;
            if (i >= N8_ALL) break;
            const float4* src; uint4* dst; int j = i;
            if (j < N8_EW1)                 { src = ew1; dst = (uint4*)g_w1h; }
            else if ((j -= N8_EW1) < N8_EW2){ src = ew2; dst = (uint4*)g_w2h; }
            else if ((j -= N8_EW2) < N8_SW1){ src = sw1; dst = (uint4*)g_sw1h; }
            else { j -= N8_SW1;               src = sw2; dst = (uint4*)g_sw2h; }
            float4 v0 = src[2 * j], v1 = src[2 * j + 1];
            __half2 h0 = __floats2half2_rn(v0.x, v0.y);
            __half2 h1 = __floats2half2_rn(v0.z, v0.w);
            __half2 h2 = __floats2half2_rn(v1.x, v1.y);
            __half2 h3 = __floats2half2_rn(v1.z, v1.w);
            uint4 w;
            w.x = *(uint32_t*)&h0; w.y = *(uint32_t*)&h1;
            w.z = *(uint32_t*)&h2; w.w = *(uint32_t*)&h3;
            dst[j] = w;
        }
        return;
    }
    int t = blockIdx.x;
    const float* xr = x + (size_t)t * DD;
    float v[4], s = 0.f, s2 = 0.f;
    #pragma unroll
    for (int i = 0; i < 4; i++) {
        v[i] = xr[tid + i * 256];
        s += v[i]; s2 += v[i] * v[i];
    }
    __shared__ float sh[16];
    block_reduce2(s, s2, sh);
    float m   = s  * (1.0f / DD);
    float var = s2 * (1.0f / DD) - m * m;
    float inv = rsqrtf(var + 1e-5f);

    __half* yr = g_xh + (size_t)t * DD;
    float p[EE];
    #pragma unroll
    for (int e = 0; e < EE; e++) p[e] = 0.f;
    #pragma unroll
    for (int i = 0; i < 4; i++) {
        int d = tid + i * 256;
        float y = (v[i] - m) * inv * g[d] + b[d];
        yr[d] = __float2half_rn(y);
        #pragma unroll
        for (int e = 0; e < EE; e++) p[e] += y * rw[e * DD + d];
    }
    __shared__ float sl[256][EE];
    #pragma unroll
    for (int e = 0; e < EE; e++) sl[tid][e] = p[e];
    __syncthreads();
    for (int o = 128; o; o >>= 1) {
        if (tid < o) {
            #pragma unroll
            for (int e = 0; e < EE; e++) sl[tid][e] += sl[tid + o][e];
        }
        __syncthreads();
    }
    if (tid == 0) {
        float l[EE];
        #pragma unroll
        for (int e = 0; e < EE; e++) l[e] = sl[0][e] + rb[e];
        int i0 = 0;
        #pragma unroll
        for (int e = 1; e < EE; e++) if (l[e] > l[i0]) i0 = e;
        int i1 = (i0 == 0) ? 1 : 0;
        #pragma unroll
        for (int e = 0; e < EE; e++) if (e != i0 && l[e] > l[i1]) i1 = e;
        float e1 = expf(l[i1] - l[i0]);
        float invp = 1.0f / (1.0f + e1);
        g_tki[2 * t] = i0;  g_tki[2 * t + 1] = i1;
        g_tkw[2 * t] = invp; g_tkw[2 * t + 1] = e1 * invp;
    }
}

// ---------------- prefix: recount g_tki (one block), then lay out segments ----------------
__global__ __launch_bounds__(256)
void prefix_kernel() {
    __shared__ int cnt[EE];
    int tid = threadIdx.x;
    if (tid < EE) cnt[tid] = 0;
    __syncthreads();
    for (int i = tid; i < TT * 2; i += 256)
        atomicAdd(&cnt[g_tki[i]], 1);
    __syncthreads();
    if (tid == 0) {
        int rowbase = 0, tile = 0;
        for (int e = 0; e < EE; e++) {
            int c = cnt[e];
            g_base[e] = rowbase;
            g_cursor[e] = 0;
            int nt = (c + 127) >> 7;
            for (int j = 0; j < nt; j++) {
                g_tile_expert[tile] = e;
                int rem = c - j * 128;
                g_tile_rows[tile] = rem < 128 ? rem : 128;
                tile++;
            }
            rowbase += nt << 7;
        }
        g_sbase = rowbase;
        for (int j = 0; j < NSHTILES; j++) {
            g_tile_expert[tile] = EE;
            g_tile_rows[tile] = 128;
            tile++;
        }
        for (; tile < MAXTILES; tile++) { g_tile_expert[tile] = -1; g_tile_rows[tile] = 0; }
    }
}

// ---------------- placement (experts + identity perm for shared segment) ----------------
__global__ void place_kernel() {
    int i = blockIdx.x * blockDim.x + threadIdx.x;
    if (i < TT * 2) {
        int e = g_tki[i];
        int pos = g_base[e] + atomicAdd(&g_cursor[e], 1);
        g_perm[pos] = i >> 1;
        g_rank[i] = pos;
    } else if (i < TT * 3) {
        int t = i - TT * 2;
        g_perm[g_sbase + t] = t;
    }
}

// ============ fp16 mma.sync GEMM: C = A @ W[e]^T + bias (2 CTAs/SM) ============
// BM=128, BN=128, BK=32 halves, 4-stage cp.async, 256 threads = 8 warps (2M x 4N),
// warp tile 64x32, rows padded to 80B. 80KB smem + <=128 regs => 2 CTAs/SM so
// one CTA's barriers/epilogue overlap the other's MMA bursts.
// WHICH 1: A gathered via g_perm, W = w1/sw1, GELU, fp16 out.
// WHICH 2: A compact rows direct, W = w2/sw2, fp32 out.
#define ROWB 80
#define A_BYTES (128 * ROWB)              // 10240
#define B_BYTES (128 * ROWB)              // 10240
#define STAGE   (A_BYTES + B_BYTES)       // 20480
#define NSTG 4
#define GEMM_SMEM (NSTG * STAGE)          // 81920

template <int WHICH>
__global__ __launch_bounds__(256, 2)
void moe_gemm(const __half* __restrict__ A,
              const __half* __restrict__ Wexp, const __half* __restrict__ Wsh,
              const float* __restrict__ bexp, const float* __restrict__ bsh,
              void* __restrict__ Cv, int N, int Kd) {
    int tileM = blockIdx.y, tileN = blockIdx.x;
    int e = g_tile_expert[tileM];
    if (e < 0) return;
    int valid = g_tile_rows[tileM];
    const __half* Bp;
    const float* bp;
    if (e < EE) {
        Bp = Wexp + (size_t)e * ((size_t)N * Kd);
        bp = bexp + (size_t)e * N;
    } else {
        Bp = Wsh;
        bp = bsh;
    }
    int row0 = tileM * 128, col0 = tileN * 128;
    int tid = threadIdx.x;
    int wid = tid >> 5, lane = tid & 31;
    int gid = lane >> 2, tig = lane & 3;
    int warpM = wid & 1, warpN = wid >> 1;   // 2 x 4

    extern __shared__ char smem[];
    uint32_t sb = smem_u32(smem);

    // ---- loaders: A 512 cpa16 (2/thread), B 512 cpa16 (2/thread) ----
    int arow = tid >> 1, apart = tid & 1;     // 2 threads/row, 32B each
    const __half* aSrc;
    if (WHICH == 1) {
        int mc = (arow < valid) ? arow : (valid - 1);
        aSrc = A + (size_t)g_perm[row0 + mc] * Kd + apart * 16;
    } else {
        aSrc = A + (size_t)(row0 + arow) * Kd + apart * 16;
    }
    const __half* bSrc = Bp + (size_t)(col0 + arow) * Kd + apart * 16;
    uint32_t aDst = sb + arow * ROWB + apart * 32;
    uint32_t bDst = sb + A_BYTES + arow * ROWB + apart * 32;

    auto load_stage = [&](int kt, int s) {   // kt in halves
        uint32_t off = s * STAGE;
        cpa16(aDst + off,      aSrc + kt);
        cpa16(aDst + off + 16, aSrc + kt + 8);
        cpa16(bDst + off,      bSrc + kt);
        cpa16(bDst + off + 16, bSrc + kt + 8);
        CP_COMMIT();
    };

    // ---- ldmatrix lane offsets ----
    uint32_t aOff[4];
    #pragma unroll
    for (int mi = 0; mi < 4; mi++)
        aOff[mi] = (uint32_t)(warpM * 64 + mi * 16 + (lane & 15)) * ROWB + (lane >> 4) * 16;
    uint32_t bOff[2];
    #pragma unroll
    for (int p = 0; p < 2; p++)
        bOff[p] = (uint32_t)A_BYTES
                + (uint32_t)(warpN * 32 + p * 16 + ((lane >> 4) << 3) + (lane & 7)) * ROWB
                + ((lane >> 3) & 1) * 16;

    float acc[4][4][4];
    #pragma unroll
    for (int mi = 0; mi < 4; mi++)
        #pragma unroll
        for (int nj = 0; nj < 4; nj++)
            #pragma unroll
            for (int q = 0; q < 4; q++) acc[mi][nj][q] = 0.f;

    int NK = Kd >> 5;   // stages of 32 halves
    load_stage(0, 0);
    load_stage(32, 1);
    load_stage(64, 2);
    CP_WAIT2();
    __syncthreads();

    for (int kt = 0; kt < NK; kt++) {
        uint32_t base = sb + (kt & 3) * STAGE;
        #pragma unroll
        for (int k16 = 0; k16 < 2; k16++) {
            uint32_t kb = k16 * 32;
            uint32_t af[4][4], bf[4][2];
            #pragma unroll
            for (int mi = 0; mi < 4; mi++)
                LDSM_X4(af[mi][0], af[mi][1], af[mi][2], af[mi][3], base + aOff[mi] + kb);
            #pragma unroll
            for (int p = 0; p < 2; p++)
                LDSM_X4(bf[2 * p][0], bf[2 * p][1], bf[2 * p + 1][0], bf[2 * p + 1][1],
                        base + bOff[p] + kb);
            #pragma unroll
            for (int mi = 0; mi < 4; mi++)
                #pragma unroll
                for (int nj = 0; nj < 4; nj++)
                    MMA_F16(acc[mi][nj], af[mi], bf[nj]);
        }
        if (kt + 3 < NK) load_stage((kt + 3) << 5, (kt + 3) & 3);
        if (kt + 1 < NK) {
            if (kt + 3 < NK)      CP_WAIT2();
            else if (kt + 2 < NK) CP_WAIT1();
            else                  CP_WAIT0();
            __syncthreads();
        }
    }

    // ---- epilogue ----
    #pragma unroll
    for (int mi = 0; mi < 4; mi++) {
        int li0 = warpM * 64 + mi * 16 + gid;
        int li1 = li0 + 8;
        bool ok0 = li0 < valid;
        bool ok1 = li1 < valid;
        #pragma unroll
        for (int nj = 0; nj < 4; nj++) {
            int c = warpN * 32 + nj * 8 + tig * 2;
            float b0 = bp[col0 + c], b1 = bp[col0 + c + 1];
            float v0 = acc[mi][nj][0] + b0;
            float v1 = acc[mi][nj][1] + b1;
            float v2 = acc[mi][nj][2] + b0;
            float v3 = acc[mi][nj][3] + b1;
            if (WHICH == 1) {
                v0 = gelu_exact(v0); v1 = gelu_exact(v1);
                v2 = gelu_exact(v2); v3 = gelu_exact(v3);
                __half* C = (__half*)Cv;
                if (ok0) *(__half2*)(C + (size_t)(row0 + li0) * N + col0 + c) = __floats2half2_rn(v0, v1);
                if (ok1) *(__half2*)(C + (size_t)(row0 + li1) * N + col0 + c) = __floats2half2_rn(v2, v3);
            } else {
                float* C = (float*)Cv;
                if (ok0) *(float2*)(C + (size_t)(row0 + li0) * N + col0 + c) = make_float2(v0, v1);
                if (ok1) *(float2*)(C + (size_t)(row0 + li1) * N + col0 + c) = make_float2(v2, v3);
            }
        }
    }
}

// ---------------- combine (shared/9 + top-2 mix) + LN2 ----------------
__global__ void combine_kernel(const float* __restrict__ g2,
                               const float* __restrict__ b2,
                               float* __restrict__ out) {
    int t = blockIdx.x, tid = threadIdx.x;
    int r0 = g_rank[2 * t], r1 = g_rank[2 * t + 1];
    float w0 = g_tkw[2 * t], w1 = g_tkw[2 * t + 1];
    const float* sh = g_eout2 + (size_t)(g_sbase + t) * OO;
    const float* e0 = g_eout2 + (size_t)r0 * OO;
    const float* e1 = g_eout2 + (size_t)r1 * OO;
    float v[4], s = 0.f, s2 = 0.f;
    #pragma unroll
    for (int i = 0; i < 4; i++) {
        int o = tid + i * 256;
        v[i] = sh[o] * (1.0f / 9.0f) + w0 * e0[o] + w1 * e1[o];
        s += v[i]; s2 += v[i] * v[i];
    }
    __shared__ float shm[16];
    block_reduce2(s, s2, shm);
    float m   = s  * (1.0f / OO);
    float var = s2 * (1.0f / OO) - m * m;
    float inv = rsqrtf(var + 1e-5f);
    float* orow = out + (size_t)t * OO;
    #pragma unroll
    for (int i = 0; i < 4; i++) {
        int o = tid + i * 256;
        orow[o] = (v[i] - m) * inv * g2[o] + b2[o];
    }
}

// ---------------- launch ----------------
extern "C" void kernel_launch(void* const* d_in, const int* in_sizes, int n_in,
                              void* d_out, int out_size) {
    const float* x        = (const float*)d_in[0];
    const float* ln1_g    = (const float*)d_in[1];
    const float* ln1_b    = (const float*)d_in[2];
    const float* router_w = (const float*)d_in[3];
    const float* router_b = (const float*)d_in[4];
    const float* sh_w1    = (const float*)d_in[5];
    const float* sh_b1    = (const float*)d_in[6];
    const float* sh_w2    = (const float*)d_in[7];
    const float* sh_b2    = (const float*)d_in[8];
    const float* e_w1     = (const float*)d_in[9];
    const float* e_b1     = (const float*)d_in[10];
    const float* e_w2     = (const float*)d_in[11];
    const float* e_b2     = (const float*)d_in[12];
    const float* ln2_g    = (const float*)d_in[13];
    const float* ln2_b    = (const float*)d_in[14];
    float* out = (float*)d_out;

    __half *p_xh, *p_hid2h, *p_w1h, *p_w2h, *p_sw1h, *p_sw2h;
    float *p_eout2;
    cudaGetSymbolAddress((void**)&p_xh,    g_xh);
    cudaGetSymbolAddress((void**)&p_hid2h, g_hid2h);
    cudaGetSymbolAddress((void**)&p_eout2, g_eout2);
    cudaGetSymbolAddress((void**)&p_w1h,   g_w1h);
    cudaGetSymbolAddress((void**)&p_w2h,   g_w2h);
    cudaGetSymbolAddress((void**)&p_sw1h,  g_sw1h);
    cudaGetSymbolAddress((void**)&p_sw2h,  g_sw2h);

    cudaFuncSetAttribute(moe_gemm<1>, cudaFuncAttributeMaxDynamicSharedMemorySize, GEMM_SMEM);
    cudaFuncSetAttribute(moe_gemm<2>, cudaFuncAttributeMaxDynamicSharedMemorySize, GEMM_SMEM);

    // fused: LN1+router (blocks 0..TT) and weight fp32->fp16 convert (remaining blocks)
    prep_kernel<<<PREP_BLOCKS, 256>>>(x, ln1_g, ln1_b, router_w, router_b,
                                      (const float4*)e_w1, (const float4*)e_w2,
                                      (const float4*)sh_w1, (const float4*)sh_w2);
    prefix_kernel<<<1, 256>>>();
    place_kernel<<<(TT * 3) / 256, 256>>>();

    // GEMM1 (gather + GELU, fp16 out): hid = gelu(x[perm] @ w1[e]^T + b1[e])
    moe_gemm<1><<<dim3(HH / 128, MAXTILES), 256, GEMM_SMEM>>>(
        p_xh, p_w1h, p_sw1h, e_b1, sh_b1, p_hid2h, HH, DD);
    // GEMM2 (compact rows, fp32 out): eout = hid @ w2[e]^T + b2[e]
    moe_gemm<2><<<dim3(OO / 128, MAXTILES), 256, GEMM_SMEM>>>(
        p_hid2h, p_w2h, p_sw2h, e_b2, sh_b2, p_eout2, OO, HH);

    combine_kernel<<<TT, 256>>>(ln2_g, ln2_b, out);
}

// round 13
// speedup vs baseline: 1.0559x; 1.0559x over previous
#include <cuda_runtime.h>
#include <cuda_fp16.h>
#include <math.h>
#include <stdint.h>

// ---------------- compile-time problem shape ----------------
#define TT 4096    // B*S tokens
#define DD 1024
#define HH 2048
#define OO 1024
#define EE 8
#define NSHTILES (TT/128)                 // 32 shared-expert tiles
#define MAXTILES (71 + NSHTILES + 1)      // expert tiles (<=71) + shared + pad
#define BUFROWS (MAXTILES*128)

// ---------------- scratch (device globals) ----------------
__device__ __half g_xh   [(size_t)TT*DD];        // LN1 output (fp16)
__device__ __half g_hid2h[(size_t)BUFROWS*HH];   // hidden, compact (fp16)
__device__ float  g_mix  [(size_t)TT*OO];        // combined expert mix (atomic accum)
__device__ __half g_w1h [(size_t)EE*HH*DD];
__device__ __half g_w2h [(size_t)EE*OO*HH];
__device__ __half g_sw1h[(size_t)HH*DD];
__device__ __half g_sw2h[(size_t)OO*HH];

__device__ int   g_tki [TT*2];
__device__ float g_tkw [TT*2];
__device__ int   g_perm[BUFROWS];
__device__ float g_roww[BUFROWS];                // per-compact-row mix weight
__device__ int   g_cursor[EE];
__device__ int   g_base[EE];
__device__ int   g_sbase;
__device__ int   g_tile_expert[MAXTILES];
__device__ int   g_tile_rows[MAXTILES];

// ---------------- PTX helpers (baseline features; legal on compute_103) ----------------
__device__ __forceinline__ uint32_t smem_u32(const void* p) {
    uint32_t a;
    asm("{ .reg .u64 t; cvta.to.shared.u64 t, %1; cvt.u32.u64 %0, t; }" : "=r"(a) : "l"(p));
    return a;
}
__device__ __forceinline__ void cpa16(uint32_t dst, const void* src) {
    asm volatile("cp.async.cg.shared.global [%0], [%1], 16;" :: "r"(dst), "l"(src));
}
#define CP_COMMIT() asm volatile("cp.async.commit_group;" ::: "memory")
#define CP_WAIT0()  asm volatile("cp.async.wait_group 0;" ::: "memory")
#define CP_WAIT1()  asm volatile("cp.async.wait_group 1;" ::: "memory")
#define CP_WAIT2()  asm volatile("cp.async.wait_group 2;" ::: "memory")

#define MMA_F16(c, a, b) \
    asm volatile("mma.sync.aligned.m16n8k16.row.col.f32.f16.f16.f32 " \
        "{%0,%1,%2,%3}, {%4,%5,%6,%7}, {%8,%9}, {%0,%1,%2,%3};" \
        : "+f"((c)[0]), "+f"((c)[1]), "+f"((c)[2]), "+f"((c)[3]) \
        : "r"((a)[0]), "r"((a)[1]), "r"((a)[2]), "r"((a)[3]), \
          "r"((b)[0]), "r"((b)[1]))

#define LDSM_X4(r0, r1, r2, r3, addr) \
    asm volatile("ldmatrix.sync.aligned.m8n8.x4.shared.b16 {%0,%1,%2,%3}, [%4];" \
        : "=r"(r0), "=r"(r1), "=r"(r2), "=r"(r3) : "r"(addr))

__device__ __forceinline__ float gelu_exact(float x) {
    return 0.5f * x * (1.0f + erff(x * 0.70710678118654752440f));
}

__device__ __forceinline__ void block_reduce2(float& s, float& s2, float* sh) {
    #pragma unroll
    for (int o = 16; o; o >>= 1) {
        s  += __shfl_down_sync(0xffffffffu, s,  o);
        s2 += __shfl_down_sync(0xffffffffu, s2, o);
    }
    int w = threadIdx.x >> 5, l = threadIdx.x & 31;
    if (l == 0) { sh[w] = s; sh[8 + w] = s2; }
    __syncthreads();
    if (threadIdx.x == 0) {
        float a = 0.f, b = 0.f;
        #pragma unroll
        for (int i = 0; i < 8; i++) { a += sh[i]; b += sh[8 + i]; }
        sh[0] = a; sh[8] = b;
    }
    __syncthreads();
    s = sh[0]; s2 = sh[8];
}

// ====== fused prep: LN1+router | weight cvt | g_mix zero ======
#define N8_EW1 (EE*HH*DD/8)
#define N8_EW2 (EE*OO*HH/8)
#define N8_SW1 (HH*DD/8)
#define N8_SW2 (OO*HH/8)
#define N8_ALL (N8_EW1 + N8_EW2 + N8_SW1 + N8_SW2)
#define CVT_BLOCKS ((N8_ALL + 4*256 - 1) / (4*256))
#define MIX4 (TT*OO/4)
#define MIX_BLOCKS ((MIX4 + 4*256 - 1) / (4*256))
#define PREP_BLOCKS (TT + CVT_BLOCKS + MIX_BLOCKS)

__global__ __launch_bounds__(256)
void prep_kernel(const float* __restrict__ x,
                 const float* __restrict__ g,
                 const float* __restrict__ b,
                 const float* __restrict__ rw,
                 const float* __restrict__ rb,
                 const float4* __restrict__ ew1, const float4* __restrict__ ew2,
                 const float4* __restrict__ sw1, const float4* __restrict__ sw2) {
    int tid = threadIdx.x;
    if (blockIdx.x >= TT + CVT_BLOCKS) {
        // ---- zero g_mix ----
        int i0 = (blockIdx.x - TT - CVT_BLOCKS) * 256 + tid;
        const int stride = MIX_BLOCKS * 256;
        float4* dst = (float4*)g_mix;
        #pragma unroll
        for (int k = 0; k < 4; k++) {
            int i = i0 + k * stride;
            if (i < MIX4) dst[i] = make_float4(0.f, 0.f, 0.f, 0.f);
        }
        return;
    }
    if (blockIdx.x >= TT) {
        // ---- weight fp32 -> fp16 ----
        int i0 = (blockIdx.x - TT) * 256 + tid;
        const int stride = CVT_BLOCKS * 256;
        #pragma unroll
        for (int k = 0; k < 4; k++) {
            int i = i0 + k * stride;
            if (i >= N8_ALL) break;
            const float4* src; uint4* dst; int j = i;
            if (j < N8_EW1)                 { src = ew1; dst = (uint4*)g_w1h; }
            else if ((j -= N8_EW1) < N8_EW2){ src = ew2; dst = (uint4*)g_w2h; }
            else if ((j -= N8_EW2) < N8_SW1){ src = sw1; dst = (uint4*)g_sw1h; }
            else { j -= N8_SW1;               src = sw2; dst = (uint4*)g_sw2h; }
            float4 v0 = src[2 * j], v1 = src[2 * j + 1];
            __half2 h0 = __floats2half2_rn(v0.x, v0.y);
            __half2 h1 = __floats2half2_rn(v0.z, v0.w);
            __half2 h2 = __floats2half2_rn(v1.x, v1.y);
            __half2 h3 = __floats2half2_rn(v1.z, v1.w);
            uint4 w;
            w.x = *(uint32_t*)&h0; w.y = *(uint32_t*)&h1;
            w.z = *(uint32_t*)&h2; w.w = *(uint32_t*)&h3;
            dst[j] = w;
        }
        return;
    }
    // ---- LN1 + router for token t ----
    int t = blockIdx.x;
    const float* xr = x + (size_t)t * DD;
    float v[4], s = 0.f, s2 = 0.f;
    #pragma unroll
    for (int i = 0; i < 4; i++) {
        v[i] = xr[tid + i * 256];
        s += v[i]; s2 += v[i] * v[i];
    }
    __shared__ float sh[16];
    block_reduce2(s, s2, sh);
    float m   = s  * (1.0f / DD);
    float var = s2 * (1.0f / DD) - m * m;
    float inv = rsqrtf(var + 1e-5f);

    __half* yr = g_xh + (size_t)t * DD;
    float p[EE];
    #pragma unroll
    for (int e = 0; e < EE; e++) p[e] = 0.f;
    #pragma unroll
    for (int i = 0; i < 4; i++) {
        int d = tid + i * 256;
        float y = (v[i] - m) * inv * g[d] + b[d];
        yr[d] = __float2half_rn(y);
        #pragma unroll
        for (int e = 0; e < EE; e++) p[e] += y * rw[e * DD + d];
    }
    __shared__ float sl[256][EE];
    #pragma unroll
    for (int e = 0; e < EE; e++) sl[tid][e] = p[e];
    __syncthreads();
    for (int o = 128; o; o >>= 1) {
        if (tid < o) {
            #pragma unroll
            for (int e = 0; e < EE; e++) sl[tid][e] += sl[tid + o][e];
        }
        __syncthreads();
    }
    if (tid == 0) {
        float l[EE];
        #pragma unroll
        for (int e = 0; e < EE; e++) l[e] = sl[0][e] + rb[e];
        int i0 = 0;
        #pragma unroll
        for (int e = 1; e < EE; e++) if (l[e] > l[i0]) i0 = e;
        int i1 = (i0 == 0) ? 1 : 0;
        #pragma unroll
        for (int e = 0; e < EE; e++) if (e != i0 && l[e] > l[i1]) i1 = e;
        float e1 = expf(l[i1] - l[i0]);
        float invp = 1.0f / (1.0f + e1);
        g_tki[2 * t] = i0;  g_tki[2 * t + 1] = i1;
        g_tkw[2 * t] = invp; g_tkw[2 * t + 1] = e1 * invp;
    }
}

// ---------------- prefix: recount g_tki (one block), then lay out segments ----------------
__global__ __launch_bounds__(256)
void prefix_kernel() {
    __shared__ int cnt[EE];
    int tid = threadIdx.x;
    if (tid < EE) cnt[tid] = 0;
    __syncthreads();
    for (int i = tid; i < TT * 2; i += 256)
        atomicAdd(&cnt[g_tki[i]], 1);
    __syncthreads();
    if (tid == 0) {
        int rowbase = 0, tile = 0;
        for (int e = 0; e < EE; e++) {
            int c = cnt[e];
            g_base[e] = rowbase;
            g_cursor[e] = 0;
            int nt = (c + 127) >> 7;
            for (int j = 0; j < nt; j++) {
                g_tile_expert[tile] = e;
                int rem = c - j * 128;
                g_tile_rows[tile] = rem < 128 ? rem : 128;
                tile++;
            }
            rowbase += nt << 7;
        }
        g_sbase = rowbase;
        for (int j = 0; j < NSHTILES; j++) {
            g_tile_expert[tile] = EE;
            g_tile_rows[tile] = 128;
            tile++;
        }
        for (; tile < MAXTILES; tile++) { g_tile_expert[tile] = -1; g_tile_rows[tile] = 0; }
    }
}

// ---------------- placement: compact perm + per-row mix weight ----------------
__global__ void place_kernel() {
    int i = blockIdx.x * blockDim.x + threadIdx.x;
    if (i < TT * 2) {
        int e = g_tki[i];
        int pos = g_base[e] + atomicAdd(&g_cursor[e], 1);
        g_perm[pos] = i >> 1;
        g_roww[pos] = g_tkw[i];
    } else if (i < TT * 3) {
        int t = i - TT * 2;
        g_perm[g_sbase + t] = t;
        g_roww[g_sbase + t] = 1.0f / 9.0f;
    }
}

// ============ fp16 mma.sync GEMM (R10 config): C = A @ W[e]^T + bias ============
// BM=128, BN=256, BK=32 halves, 4-stage cp.async, 512 threads = 16 warps (2M x 8N),
// warp tile 64x32, rows padded to 80B.
// WHICH 1: A gathered via g_perm, W = w1/sw1, GELU, fp16 out to hid buffer.
// WHICH 2: A compact rows direct, W = w2/sw2; epilogue scatters w*(acc+bias)
//          into g_mix[token] via atomicAdd (fused combine).
#define ROWB 80
#define A_BYTES (128 * ROWB)              // 10240
#define B_BYTES (256 * ROWB)              // 20480
#define STAGE   (A_BYTES + B_BYTES)       // 30720
#define NSTG 4
#define GEMM_SMEM (NSTG * STAGE)          // 122880

template <int WHICH>
__global__ __launch_bounds__(512, 1)
void moe_gemm(const __half* __restrict__ A,
              const __half* __restrict__ Wexp, const __half* __restrict__ Wsh,
              const float* __restrict__ bexp, const float* __restrict__ bsh,
              void* __restrict__ Cv, int N, int Kd) {
    int tileM = blockIdx.y, tileN = blockIdx.x;
    int e = g_tile_expert[tileM];
    if (e < 0) return;
    int valid = g_tile_rows[tileM];
    const __half* Bp;
    const float* bp;
    if (e < EE) {
        Bp = Wexp + (size_t)e * ((size_t)N * Kd);
        bp = bexp + (size_t)e * N;
    } else {
        Bp = Wsh;
        bp = bsh;
    }
    int row0 = tileM * 128, col0 = tileN * 256;
    int tid = threadIdx.x;
    int wid = tid >> 5, lane = tid & 31;
    int gid = lane >> 2, tig = lane & 3;
    int warpM = wid & 1, warpN = wid >> 1;   // 2 x 8

    extern __shared__ char smem[];
    uint32_t sb = smem_u32(smem);

    // ---- loaders: A 512 cpa16 (1/thread), B 1024 cpa16 (2/thread) ----
    int arow = tid >> 2, achk = tid & 3;
    const __half* aSrc;
    if (WHICH == 1) {
        int mc = (arow < valid) ? arow : (valid - 1);
        aSrc = A + (size_t)g_perm[row0 + mc] * Kd + achk * 8;
    } else {
        aSrc = A + (size_t)(row0 + arow) * Kd + achk * 8;
    }
    const __half* b0Src = Bp + (size_t)(col0 + arow) * Kd + achk * 8;
    const __half* b1Src = Bp + (size_t)(col0 + 128 + arow) * Kd + achk * 8;
    uint32_t aDst  = sb + arow * ROWB + achk * 16;
    uint32_t b0Dst = sb + A_BYTES + arow * ROWB + achk * 16;
    uint32_t b1Dst = sb + A_BYTES + (128 + arow) * ROWB + achk * 16;

    auto load_stage = [&](int kt, int s) {   // kt in halves
        uint32_t off = s * STAGE;
        cpa16(aDst + off,  aSrc + kt);
        cpa16(b0Dst + off, b0Src + kt);
        cpa16(b1Dst + off, b1Src + kt);
        CP_COMMIT();
    };

    // ---- ldmatrix lane offsets ----
    uint32_t aOff[4];
    #pragma unroll
    for (int mi = 0; mi < 4; mi++)
        aOff[mi] = (uint32_t)(warpM * 64 + mi * 16 + (lane & 15)) * ROWB + (lane >> 4) * 16;
    uint32_t bOff[2];
    #pragma unroll
    for (int p = 0; p < 2; p++)
        bOff[p] = (uint32_t)A_BYTES
                + (uint32_t)(warpN * 32 + p * 16 + ((lane >> 4) << 3) + (lane & 7)) * ROWB
                + ((lane >> 3) & 1) * 16;

    float acc[4][4][4];
    #pragma unroll
    for (int mi = 0; mi < 4; mi++)
        #pragma unroll
        for (int nj = 0; nj < 4; nj++)
            #pragma unroll
            for (int q = 0; q < 4; q++) acc[mi][nj][q] = 0.f;

    int NK = Kd >> 5;   // stages of 32 halves
    load_stage(0, 0);
    load_stage(32, 1);
    load_stage(64, 2);
    CP_WAIT2();
    __syncthreads();

    for (int kt = 0; kt < NK; kt++) {
        uint32_t base = sb + (kt & 3) * STAGE;
        #pragma unroll
        for (int k16 = 0; k16 < 2; k16++) {
            uint32_t kb = k16 * 32;
            uint32_t af[4][4], bf[4][2];
            #pragma unroll
            for (int mi = 0; mi < 4; mi++)
                LDSM_X4(af[mi][0], af[mi][1], af[mi][2], af[mi][3], base + aOff[mi] + kb);
            #pragma unroll
            for (int p = 0; p < 2; p++)
                LDSM_X4(bf[2 * p][0], bf[2 * p][1], bf[2 * p + 1][0], bf[2 * p + 1][1],
                        base + bOff[p] + kb);
            #pragma unroll
            for (int mi = 0; mi < 4; mi++)
                #pragma unroll
                for (int nj = 0; nj < 4; nj++)
                    MMA_F16(acc[mi][nj], af[mi], bf[nj]);
        }
        if (kt + 3 < NK) load_stage((kt + 3) << 5, (kt + 3) & 3);
        if (kt + 1 < NK) {
            if (kt + 3 < NK)      CP_WAIT2();
            else if (kt + 2 < NK) CP_WAIT1();
            else                  CP_WAIT0();
            __syncthreads();
        }
    }

    // ---- epilogue ----
    #pragma unroll
    for (int mi = 0; mi < 4; mi++) {
        int li0 = warpM * 64 + mi * 16 + gid;
        int li1 = li0 + 8;
        bool ok0 = li0 < valid;
        bool ok1 = li1 < valid;
        if (WHICH == 1) {
            __half* C = (__half*)Cv;
            #pragma unroll
            for (int nj = 0; nj < 4; nj++) {
                int c = warpN * 32 + nj * 8 + tig * 2;
                float b0 = bp[col0 + c], b1 = bp[col0 + c + 1];
                float v0 = gelu_exact(acc[mi][nj][0] + b0);
                float v1 = gelu_exact(acc[mi][nj][1] + b1);
                float v2 = gelu_exact(acc[mi][nj][2] + b0);
                float v3 = gelu_exact(acc[mi][nj][3] + b1);
                if (ok0) *(__half2*)(C + (size_t)(row0 + li0) * N + col0 + c) = __floats2half2_rn(v0, v1);
                if (ok1) *(__half2*)(C + (size_t)(row0 + li1) * N + col0 + c) = __floats2half2_rn(v2, v3);
            }
        } else {
            // fused combine: g_mix[token] += w * (acc + bias)
            int   t0 = ok0 ? g_perm[row0 + li0] : 0;
            int   t1 = ok1 ? g_perm[row0 + li1] : 0;
            float w0r = ok0 ? g_roww[row0 + li0] : 0.f;
            float w1r = ok1 ? g_roww[row0 + li1] : 0.f;
            float* d0 = g_mix + (size_t)t0 * OO + col0;
            float* d1 = g_mix + (size_t)t1 * OO + col0;
            #pragma unroll
            for (int nj = 0; nj < 4; nj++) {
                int c = warpN * 32 + nj * 8 + tig * 2;
                float b0 = bp[col0 + c], b1 = bp[col0 + c + 1];
                if (ok0) {
                    atomicAdd(&d0[c],     w0r * (acc[mi][nj][0] + b0));
                    atomicAdd(&d0[c + 1], w0r * (acc[mi][nj][1] + b1));
                }
                if (ok1) {
                    atomicAdd(&d1[c],     w1r * (acc[mi][nj][2] + b0));
                    atomicAdd(&d1[c + 1], w1r * (acc[mi][nj][3] + b1));
                }
            }
        }
    }
}

// ---------------- LN2 over g_mix ----------------
__global__ void ln2_kernel(const float* __restrict__ g2,
                           const float* __restrict__ b2,
                           float* __restrict__ out) {
    int t = blockIdx.x, tid = threadIdx.x;
    const float* mr = g_mix + (size_t)t * OO;
    float v[4], s = 0.f, s2 = 0.f;
    #pragma unroll
    for (int i = 0; i < 4; i++) {
        int o = tid + i * 256;
        v[i] = mr[o];
        s += v[i]; s2 += v[i] * v[i];
    }
    __shared__ float shm[16];
    block_reduce2(s, s2, shm);
    float m   = s  * (1.0f / OO);
    float var = s2 * (1.0f / OO) - m * m;
    float inv = rsqrtf(var + 1e-5f);
    float* orow = out + (size_t)t * OO;
    #pragma unroll
    for (int i = 0; i < 4; i++) {
        int o = tid + i * 256;
        orow[o] = (v[i] - m) * inv * g2[o] + b2[o];
    }
}

// ---------------- launch ----------------
extern "C" void kernel_launch(void* const* d_in, const int* in_sizes, int n_in,
                              void* d_out, int out_size) {
    const float* x        = (const float*)d_in[0];
    const float* ln1_g    = (const float*)d_in[1];
    const float* ln1_b    = (const float*)d_in[2];
    const float* router_w = (const float*)d_in[3];
    const float* router_b = (const float*)d_in[4];
    const float* sh_w1    = (const float*)d_in[5];
    const float* sh_b1    = (const float*)d_in[6];
    const float* sh_w2    = (const float*)d_in[7];
    const float* sh_b2    = (const float*)d_in[8];
    const float* e_w1     = (const float*)d_in[9];
    const float* e_b1     = (const float*)d_in[10];
    const float* e_w2     = (const float*)d_in[11];
    const float* e_b2     = (const float*)d_in[12];
    const float* ln2_g    = (const float*)d_in[13];
    const float* ln2_b    = (const float*)d_in[14];
    float* out = (float*)d_out;

    __half *p_xh, *p_hid2h, *p_w1h, *p_w2h, *p_sw1h, *p_sw2h;
    cudaGetSymbolAddress((void**)&p_xh,    g_xh);
    cudaGetSymbolAddress((void**)&p_hid2h, g_hid2h);
    cudaGetSymbolAddress((void**)&p_w1h,   g_w1h);
    cudaGetSymbolAddress((void**)&p_w2h,   g_w2h);
    cudaGetSymbolAddress((void**)&p_sw1h,  g_sw1h);
    cudaGetSymbolAddress((void**)&p_sw2h,  g_sw2h);

    cudaFuncSetAttribute(moe_gemm<1>, cudaFuncAttributeMaxDynamicSharedMemorySize, GEMM_SMEM);
    cudaFuncSetAttribute(moe_gemm<2>, cudaFuncAttributeMaxDynamicSharedMemorySize, GEMM_SMEM);

    // fused: LN1+router | weight cvt | g_mix zero
    prep_kernel<<<PREP_BLOCKS, 256>>>(x, ln1_g, ln1_b, router_w, router_b,
                                      (const float4*)e_w1, (const float4*)e_w2,
                                      (const float4*)sh_w1, (const float4*)sh_w2);
    prefix_kernel<<<1, 256>>>();
    place_kernel<<<(TT * 3) / 256, 256>>>();

    // GEMM1 (gather + GELU, fp16 out): hid = gelu(x[perm] @ w1[e]^T + b1[e])
    moe_gemm<1><<<dim3(HH / 256, MAXTILES), 512, GEMM_SMEM>>>(
        p_xh, p_w1h, p_sw1h, e_b1, sh_b1, p_hid2h, HH, DD);
    // GEMM2 (compact rows) with fused combine scatter into g_mix
    moe_gemm<2><<<dim3(OO / 256, MAXTILES), 512, GEMM_SMEM>>>(
        p_hid2h, p_w2h, p_sw2h, e_b2, sh_b2, nullptr, OO, HH);

    ln2_kernel<<<TT, 256>>>(ln2_g, ln2_b, out);
}

// round 14
// speedup vs baseline: 1.1633x; 1.1017x over previous
#include <cuda_runtime.h>
#include <cuda_fp16.h>
#include <math.h>
#include <stdint.h>

// ---------------- compile-time problem shape ----------------
#define TT 4096    // B*S tokens
#define DD 1024
#define HH 2048
#define OO 1024
#define EE 8
#define NSHTILES (TT/128)                 // 32 shared-expert tiles
#define MAXTILES (71 + NSHTILES + 1)      // expert tiles (<=71) + shared + pad
#define BUFROWS (MAXTILES*128)
#define NPERS 152                         // persistent CTAs (GB300: 152 SMs)

// ---------------- scratch (device globals) ----------------
__device__ __half g_xh   [(size_t)TT*DD];        // LN1 output (fp16)
__device__ __half g_hid2h[(size_t)BUFROWS*HH];   // hidden, compact (fp16)
__device__ float  g_eout2[(size_t)BUFROWS*OO];   // output, compact (fp32)
__device__ __half g_w1h [(size_t)EE*HH*DD];
__device__ __half g_w2h [(size_t)EE*OO*HH];
__device__ __half g_sw1h[(size_t)HH*DD];
__device__ __half g_sw2h[(size_t)OO*HH];

__device__ int   g_tki [TT*2];
__device__ float g_tkw [TT*2];
__device__ int   g_rank[TT*2];
__device__ int   g_perm[BUFROWS];
__device__ int   g_cursor[EE];
__device__ int   g_base[EE];
__device__ int   g_sbase;
__device__ int   g_ntiles;                       // real tile count
__device__ int   g_ctr1, g_ctr2;                 // persistent work counters
__device__ int   g_tile_expert[MAXTILES];
__device__ int   g_tile_rows[MAXTILES];

// ---------------- PTX helpers (baseline features; legal on compute_103) ----------------
__device__ __forceinline__ uint32_t smem_u32(const void* p) {
    uint32_t a;
    asm("{ .reg .u64 t; cvta.to.shared.u64 t, %1; cvt.u32.u64 %0, t; }" : "=r"(a) : "l"(p));
    return a;
}
__device__ __forceinline__ void cpa16(uint32_t dst, const void* src) {
    asm volatile("cp.async.cg.shared.global [%0], [%1], 16;" :: "r"(dst), "l"(src));
}
#define CP_COMMIT() asm volatile("cp.async.commit_group;" ::: "memory")
#define CP_WAIT0()  asm volatile("cp.async.wait_group 0;" ::: "memory")
#define CP_WAIT1()  asm volatile("cp.async.wait_group 1;" ::: "memory")
#define CP_WAIT2()  asm volatile("cp.async.wait_group 2;" ::: "memory")

#define MMA_F16(c, a, b) \
    asm volatile("mma.sync.aligned.m16n8k16.row.col.f32.f16.f16.f32 " \
        "{%0,%1,%2,%3}, {%4,%5,%6,%7}, {%8,%9}, {%0,%1,%2,%3};" \
        : "+f"((c)[0]), "+f"((c)[1]), "+f"((c)[2]), "+f"((c)[3]) \
        : "r"((a)[0]), "r"((a)[1]), "r"((a)[2]), "r"((a)[3]), \
          "r"((b)[0]), "r"((b)[1]))

#define LDSM_X4(r0, r1, r2, r3, addr) \
    asm volatile("ldmatrix.sync.aligned.m8n8.x4.shared.b16 {%0,%1,%2,%3}, [%4];" \
        : "=r"(r0), "=r"(r1), "=r"(r2), "=r"(r3) : "r"(addr))

__device__ __forceinline__ float gelu_exact(float x) {
    return 0.5f * x * (1.0f + erff(x * 0.70710678118654752440f));
}

__device__ __forceinline__ void block_reduce2(float& s, float& s2, float* sh) {
    #pragma unroll
    for (int o = 16; o; o >>= 1) {
        s  += __shfl_down_sync(0xffffffffu, s,  o);
        s2 += __shfl_down_sync(0xffffffffu, s2, o);
    }
    int w = threadIdx.x >> 5, l = threadIdx.x & 31;
    if (l == 0) { sh[w] = s; sh[8 + w] = s2; }
    __syncthreads();
    if (threadIdx.x == 0) {
        float a = 0.f, b = 0.f;
        #pragma unroll
        for (int i = 0; i < 8; i++) { a += sh[i]; b += sh[8 + i]; }
        sh[0] = a; sh[8] = b;
    }
    __syncthreads();
    s = sh[0]; s2 = sh[8];
}

// ====== fused prep: LN1+router (blocks 0..TT) | weight cvt (rest) ======
#define N8_EW1 (EE*HH*DD/8)
#define N8_EW2 (EE*OO*HH/8)
#define N8_SW1 (HH*DD/8)
#define N8_SW2 (OO*HH/8)
#define N8_ALL (N8_EW1 + N8_EW2 + N8_SW1 + N8_SW2)
#define CVT_BLOCKS ((N8_ALL + 4*256 - 1) / (4*256))
#define PREP_BLOCKS (TT + CVT_BLOCKS)

__global__ __launch_bounds__(256)
void prep_kernel(const float* __restrict__ x,
                 const float* __restrict__ g,
                 const float* __restrict__ b,
                 const float* __restrict__ rw,
                 const float* __restrict__ rb,
                 const float4* __restrict__ ew1, const float4* __restrict__ ew2,
                 const float4* __restrict__ sw1, const float4* __restrict__ sw2) {
    int tid = threadIdx.x;
    if (blockIdx.x >= TT) {
        int i0 = (blockIdx.x - TT) * 256 + tid;
        const int stride = CVT_BLOCKS * 256;
        #pragma unroll
        for (int k = 0; k < 4; k++) {
            int i = i0 + k * stride;
            if (i >= N8_ALL) break;
            const float4* src; uint4* dst; int j = i;
            if (j < N8_EW1)                 { src = ew1; dst = (uint4*)g_w1h; }
            else if ((j -= N8_EW1) < N8_EW2){ src = ew2; dst = (uint4*)g_w2h; }
            else if ((j -= N8_EW2) < N8_SW1){ src = sw1; dst = (uint4*)g_sw1h; }
            else { j -= N8_SW1;               src = sw2; dst = (uint4*)g_sw2h; }
            float4 v0 = src[2 * j], v1 = src[2 * j + 1];
            __half2 h0 = __floats2half2_rn(v0.x, v0.y);
            __half2 h1 = __floats2half2_rn(v0.z, v0.w);
            __half2 h2 = __floats2half2_rn(v1.x, v1.y);
            __half2 h3 = __floats2half2_rn(v1.z, v1.w);
            uint4 w;
            w.x = *(uint32_t*)&h0; w.y = *(uint32_t*)&h1;
            w.z = *(uint32_t*)&h2; w.w = *(uint32_t*)&h3;
            dst[j] = w;
        }
        return;
    }
    int t = blockIdx.x;
    const float* xr = x + (size_t)t * DD;
    float v[4], s = 0.f, s2 = 0.f;
    #pragma unroll
    for (int i = 0; i < 4; i++) {
        v[i] = xr[tid + i * 256];
        s += v[i]; s2 += v[i] * v[i];
    }
    __shared__ float sh[16];
    block_reduce2(s, s2, sh);
    float m   = s  * (1.0f / DD);
    float var = s2 * (1.0f / DD) - m * m;
    float inv = rsqrtf(var + 1e-5f);

    __half* yr = g_xh + (size_t)t * DD;
    float p[EE];
    #pragma unroll
    for (int e = 0; e < EE; e++) p[e] = 0.f;
    #pragma unroll
    for (int i = 0; i < 4; i++) {
        int d = tid + i * 256;
        float y = (v[i] - m) * inv * g[d] + b[d];
        yr[d] = __float2half_rn(y);
        #pragma unroll
        for (int e = 0; e < EE; e++) p[e] += y * rw[e * DD + d];
    }
    __shared__ float sl[256][EE];
    #pragma unroll
    for (int e = 0; e < EE; e++) sl[tid][e] = p[e];
    __syncthreads();
    for (int o = 128; o; o >>= 1) {
        if (tid < o) {
            #pragma unroll
            for (int e = 0; e < EE; e++) sl[tid][e] += sl[tid + o][e];
        }
        __syncthreads();
    }
    if (tid == 0) {
        float l[EE];
        #pragma unroll
        for (int e = 0; e < EE; e++) l[e] = sl[0][e] + rb[e];
        int i0 = 0;
        #pragma unroll
        for (int e = 1; e < EE; e++) if (l[e] > l[i0]) i0 = e;
        int i1 = (i0 == 0) ? 1 : 0;
        #pragma unroll
        for (int e = 0; e < EE; e++) if (e != i0 && l[e] > l[i1]) i1 = e;
        float e1 = expf(l[i1] - l[i0]);
        float invp = 1.0f / (1.0f + e1);
        g_tki[2 * t] = i0;  g_tki[2 * t + 1] = i1;
        g_tkw[2 * t] = invp; g_tkw[2 * t + 1] = e1 * invp;
    }
}

// ---------------- prefix: recount g_tki, lay out segments, reset work counters ----------------
__global__ __launch_bounds__(256)
void prefix_kernel() {
    __shared__ int cnt[EE];
    int tid = threadIdx.x;
    if (tid < EE) cnt[tid] = 0;
    __syncthreads();
    for (int i = tid; i < TT * 2; i += 256)
        atomicAdd(&cnt[g_tki[i]], 1);
    __syncthreads();
    if (tid == 0) {
        int rowbase = 0, tile = 0;
        for (int e = 0; e < EE; e++) {
            int c = cnt[e];
            g_base[e] = rowbase;
            g_cursor[e] = 0;
            int nt = (c + 127) >> 7;
            for (int j = 0; j < nt; j++) {
                g_tile_expert[tile] = e;
                int rem = c - j * 128;
                g_tile_rows[tile] = rem < 128 ? rem : 128;
                tile++;
            }
            rowbase += nt << 7;
        }
        g_sbase = rowbase;
        for (int j = 0; j < NSHTILES; j++) {
            g_tile_expert[tile] = EE;
            g_tile_rows[tile] = 128;
            tile++;
        }
        g_ntiles = tile;
        g_ctr1 = 0;
        g_ctr2 = 0;
        for (; tile < MAXTILES; tile++) { g_tile_expert[tile] = -1; g_tile_rows[tile] = 0; }
    }
}

// ---------------- placement (experts + identity perm for shared segment) ----------------
__global__ void place_kernel() {
    int i = blockIdx.x * blockDim.x + threadIdx.x;
    if (i < TT * 2) {
        int e = g_tki[i];
        int pos = g_base[e] + atomicAdd(&g_cursor[e], 1);
        g_perm[pos] = i >> 1;
        g_rank[i] = pos;
    } else if (i < TT * 3) {
        int t = i - TT * 2;
        g_perm[g_sbase + t] = t;
    }
}

// ============ persistent fp16 mma.sync GEMM: C = A @ W[e]^T + bias ============
// BM=128, BN=256, BK=32 halves, 4-stage cp.async ring that CONTINUES ACROSS TILES
// (prologue/epilogue of consecutive tiles overlap). 512 threads = 16 warps (2M x 8N),
// warp tile 64x32, rows padded to 80B. Work items = tile grid, atomic dispatch.
// WHICH 1: A gathered via g_perm, W = w1/sw1, GELU, fp16 out.
// WHICH 2: A compact rows direct, W = w2/sw2, fp32 out.
#define ROWB 80
#define A_BYTES (128 * ROWB)              // 10240
#define B_BYTES (256 * ROWB)              // 20480
#define STAGE   (A_BYTES + B_BYTES)       // 30720
#define GEMM_SMEM (4 * STAGE)             // 122880

template <int WHICH, int NDIM, int KDIM>
__global__ __launch_bounds__(512)
void moe_gemm(const __half* __restrict__ A,
              const __half* __restrict__ Wexp, const __half* __restrict__ Wsh,
              const float* __restrict__ bexp, const float* __restrict__ bsh,
              void* __restrict__ Cv) {
    constexpr int NTN = NDIM / 256;
    constexpr int NK  = KDIM / 32;
    int* ctr = (WHICH == 1) ? &g_ctr1 : &g_ctr2;

    extern __shared__ char smem[];
    __shared__ int s_next, s_total;
    uint32_t sb = smem_u32(smem);
    int tid = threadIdx.x;
    int wid = tid >> 5, lane = tid & 31;
    int gid = lane >> 2, tig = lane & 3;
    int warpM = wid & 1, warpN = wid >> 1;   // 2 x 8

    // loader mapping (fixed per thread)
    int arow = tid >> 2, achk = tid & 3;
    uint32_t aDst  = sb + arow * ROWB + achk * 16;
    uint32_t b0Dst = sb + A_BYTES + arow * ROWB + achk * 16;
    uint32_t b1Dst = sb + A_BYTES + (128 + arow) * ROWB + achk * 16;

    // ldmatrix lane offsets
    uint32_t aOff[4];
    #pragma unroll
    for (int mi = 0; mi < 4; mi++)
        aOff[mi] = (uint32_t)(warpM * 64 + mi * 16 + (lane & 15)) * ROWB + (lane >> 4) * 16;
    uint32_t bOff[2];
    #pragma unroll
    for (int p = 0; p < 2; p++)
        bOff[p] = (uint32_t)A_BYTES
                + (uint32_t)(warpN * 32 + p * 16 + ((lane >> 4) << 3) + (lane & 7)) * ROWB
                + ((lane >> 3) & 1) * 16;

    if (tid == 0) { s_total = g_ntiles * NTN; s_next = atomicAdd(ctr, 1); }
    __syncthreads();
    const int total = s_total;
    int wcur = s_next;
    if (wcur >= total) return;

    // fetch-side tile pointers (this thread's)
    const __half *fa, *fb0, *fb1;
    auto make_tile = [&](int w) {
        int tM = w / NTN, tN = w % NTN;
        int r0 = tM * 128, c0 = tN * 256;
        const __half* Bp;
        int ee = g_tile_expert[tM];
        if (ee < EE) Bp = Wexp + (size_t)ee * ((size_t)NDIM * KDIM);
        else         Bp = Wsh;
        if (WHICH == 1) {
            int vd = g_tile_rows[tM];
            int mc = (arow < vd) ? arow : (vd - 1);
            fa = A + (size_t)g_perm[r0 + mc] * KDIM + achk * 8;
        } else {
            fa = A + (size_t)(r0 + arow) * KDIM + achk * 8;
        }
        fb0 = Bp + (size_t)(c0 + arow) * KDIM + achk * 8;
        fb1 = Bp + (size_t)(c0 + 128 + arow) * KDIM + achk * 8;
    };

    make_tile(wcur);
    int wfet = wcur, fkt = 0;
    int pending = 0, wslot = 0, rdslot = 0;

    __syncthreads();                        // everyone read s_next(first)
    if (tid == 0) s_next = atomicAdd(ctr, 1);   // grab next work (published by iter-0 barrier)

    auto fetch_one = [&]() {
        if (wfet < 0) return;
        uint32_t off = (uint32_t)wslot * STAGE;
        int kb = fkt << 5;
        cpa16(aDst + off,  fa + kb);
        cpa16(b0Dst + off, fb0 + kb);
        cpa16(b1Dst + off, fb1 + kb);
        CP_COMMIT();
        pending++;
        wslot = (wslot + 1) & 3;
        if (++fkt == NK) {
            fkt = 0;
            int wn = s_next;                // safe: >=1 barrier since write, >=3 barriers before rewrite
            if (wn < total) { wfet = wn; make_tile(wn); }
            else wfet = -1;
        }
    };

    fetch_one(); fetch_one(); fetch_one();  // prologue (NK >= 4 always)

    for (;;) {
        float acc[4][4][4];
        #pragma unroll
        for (int mi = 0; mi < 4; mi++)
            #pragma unroll
            for (int nj = 0; nj < 4; nj++)
                #pragma unroll
                for (int q = 0; q < 4; q++) acc[mi][nj][q] = 0.f;

        for (int kt = 0; kt < NK; kt++) {
            if (pending >= 3)      CP_WAIT2();
            else if (pending == 2) CP_WAIT1();
            else                   CP_WAIT0();
            __syncthreads();
            pending--;
            uint32_t base = sb + (uint32_t)rdslot * STAGE;
            rdslot = (rdslot + 1) & 3;
            #pragma unroll
            for (int k16 = 0; k16 < 2; k16++) {
                uint32_t kb = k16 * 32;
                uint32_t af[4][4], bf[4][2];
                #pragma unroll
                for (int mi = 0; mi < 4; mi++)
                    LDSM_X4(af[mi][0], af[mi][1], af[mi][2], af[mi][3], base + aOff[mi] + kb);
                #pragma unroll
                for (int p = 0; p < 2; p++)
                    LDSM_X4(bf[2 * p][0], bf[2 * p][1], bf[2 * p + 1][0], bf[2 * p + 1][1],
                            base + bOff[p] + kb);
                #pragma unroll
                for (int mi = 0; mi < 4; mi++)
                    #pragma unroll
                    for (int nj = 0; nj < 4; nj++)
                        MMA_F16(acc[mi][nj], af[mi], bf[nj]);
            }
            fetch_one();
        }

        // ---- epilogue for wcur (recompute tile scalars; L2-hot) ----
        {
            int tM = wcur / NTN, tN = wcur % NTN;
            int row0 = tM * 128, col0 = tN * 256;
            int valid = g_tile_rows[tM];
            int ee = g_tile_expert[tM];
            const float* bp = (ee < EE) ? bexp + (size_t)ee * NDIM : bsh;
            #pragma unroll
            for (int mi = 0; mi < 4; mi++) {
                int li0 = warpM * 64 + mi * 16 + gid;
                int li1 = li0 + 8;
                bool ok0 = li0 < valid;
                bool ok1 = li1 < valid;
                #pragma unroll
                for (int nj = 0; nj < 4; nj++) {
                    int c = warpN * 32 + nj * 8 + tig * 2;
                    float b0 = bp[col0 + c], b1 = bp[col0 + c + 1];
                    float v0 = acc[mi][nj][0] + b0;
                    float v1 = acc[mi][nj][1] + b1;
                    float v2 = acc[mi][nj][2] + b0;
                    float v3 = acc[mi][nj][3] + b1;
                    if (WHICH == 1) {
                        v0 = gelu_exact(v0); v1 = gelu_exact(v1);
                        v2 = gelu_exact(v2); v3 = gelu_exact(v3);
                        __half* C = (__half*)Cv;
                        if (ok0) *(__half2*)(C + (size_t)(row0 + li0) * NDIM + col0 + c) = __floats2half2_rn(v0, v1);
                        if (ok1) *(__half2*)(C + (size_t)(row0 + li1) * NDIM + col0 + c) = __floats2half2_rn(v2, v3);
                    } else {
                        float* C = (float*)Cv;
                        if (ok0) *(float2*)(C + (size_t)(row0 + li0) * NDIM + col0 + c) = make_float2(v0, v1);
                        if (ok1) *(float2*)(C + (size_t)(row0 + li1) * NDIM + col0 + c) = make_float2(v2, v3);
                    }
                }
            }
        }

        if (wfet < 0) return;          // no next tile; pending drained to 0
        wcur = wfet;
        __syncthreads();               // all threads past crossing-read of s_next
        if (tid == 0) s_next = atomicAdd(ctr, 1);
    }
}

// ---------------- combine (shared/9 + top-2 mix) + LN2 ----------------
__global__ void combine_kernel(const float* __restrict__ g2,
                               const float* __restrict__ b2,
                               float* __restrict__ out) {
    int t = blockIdx.x, tid = threadIdx.x;
    int r0 = g_rank[2 * t], r1 = g_rank[2 * t + 1];
    float w0 = g_tkw[2 * t], w1 = g_tkw[2 * t + 1];
    const float* sh = g_eout2 + (size_t)(g_sbase + t) * OO;
    const float* e0 = g_eout2 + (size_t)r0 * OO;
    const float* e1 = g_eout2 + (size_t)r1 * OO;
    float v[4], s = 0.f, s2 = 0.f;
    #pragma unroll
    for (int i = 0; i < 4; i++) {
        int o = tid + i * 256;
        v[i] = sh[o] * (1.0f / 9.0f) + w0 * e0[o] + w1 * e1[o];
        s += v[i]; s2 += v[i] * v[i];
    }
    __shared__ float shm[16];
    block_reduce2(s, s2, shm);
    float m   = s  * (1.0f / OO);
    float var = s2 * (1.0f / OO) - m * m;
    float inv = rsqrtf(var + 1e-5f);
    float* orow = out + (size_t)t * OO;
    #pragma unroll
    for (int i = 0; i < 4; i++) {
        int o = tid + i * 256;
        orow[o] = (v[i] - m) * inv * g2[o] + b2[o];
    }
}

// ---------------- launch ----------------
extern "C" void kernel_launch(void* const* d_in, const int* in_sizes, int n_in,
                              void* d_out, int out_size) {
    const float* x        = (const float*)d_in[0];
    const float* ln1_g    = (const float*)d_in[1];
    const float* ln1_b    = (const float*)d_in[2];
    const float* router_w = (const float*)d_in[3];
    const float* router_b = (const float*)d_in[4];
    const float* sh_w1    = (const float*)d_in[5];
    const float* sh_b1    = (const float*)d_in[6];
    const float* sh_w2    = (const float*)d_in[7];
    const float* sh_b2    = (const float*)d_in[8];
    const float* e_w1     = (const float*)d_in[9];
    const float* e_b1     = (const float*)d_in[10];
    const float* e_w2     = (const float*)d_in[11];
    const float* e_b2     = (const float*)d_in[12];
    const float* ln2_g    = (const float*)d_in[13];
    const float* ln2_b    = (const float*)d_in[14];
    float* out = (float*)d_out;

    __half *p_xh, *p_hid2h, *p_w1h, *p_w2h, *p_sw1h, *p_sw2h;
    float *p_eout2;
    cudaGetSymbolAddress((void**)&p_xh,    g_xh);
    cudaGetSymbolAddress((void**)&p_hid2h, g_hid2h);
    cudaGetSymbolAddress((void**)&p_eout2, g_eout2);
    cudaGetSymbolAddress((void**)&p_w1h,   g_w1h);
    cudaGetSymbolAddress((void**)&p_w2h,   g_w2h);
    cudaGetSymbolAddress((void**)&p_sw1h,  g_sw1h);
    cudaGetSymbolAddress((void**)&p_sw2h,  g_sw2h);

    cudaFuncSetAttribute((const void*)moe_gemm<1, HH, DD>, cudaFuncAttributeMaxDynamicSharedMemorySize, GEMM_SMEM);
    cudaFuncSetAttribute((const void*)moe_gemm<2, OO, HH>, cudaFuncAttributeMaxDynamicSharedMemorySize, GEMM_SMEM);

    // fused: LN1+router (blocks 0..TT) and weight fp32->fp16 convert (remaining blocks)
    prep_kernel<<<PREP_BLOCKS, 256>>>(x, ln1_g, ln1_b, router_w, router_b,
                                      (const float4*)e_w1, (const float4*)e_w2,
                                      (const float4*)sh_w1, (const float4*)sh_w2);
    prefix_kernel<<<1, 256>>>();
    place_kernel<<<(TT * 3) / 256, 256>>>();

    // persistent GEMM1 (gather + GELU, fp16 out): hid = gelu(x[perm] @ w1[e]^T + b1[e])
    moe_gemm<1, HH, DD><<<NPERS, 512, GEMM_SMEM>>>(
        p_xh, p_w1h, p_sw1h, e_b1, sh_b1, p_hid2h);
    // persistent GEMM2 (compact rows, fp32 out): eout = hid @ w2[e]^T + b2[e]
    moe_gemm<2, OO, HH><<<NPERS, 512, GEMM_SMEM>>>(
        p_hid2h, p_w2h, p_sw2h, e_b2, sh_b2, p_eout2);

    combine_kernel<<<TT, 256>>>(ln2_g, ln2_b, out);
}